// round 9
// baseline (speedup 1.0000x reference)
#include <cuda_runtime.h>
#include <cuda_fp16.h>
#include <cstdint>
#include <cstddef>

// B=128, S=2048, I=256, H=512, O=256
// Persistent fp16 LSTM, weights-in-registers, register epilogue:
//  128 CTAs = 4 batch-bands(32 rows) x 32 column-CTAs(16 h-cols x 4 gates).
//  n-ordering = hc*4+gate  =>  thread-pair (tq even/odd) holds all 4 gates of
//  one (row, h-col); two parity-selected shfl.bfly assemble full gate sets.
//  Cell state + bias live in registers. No smem epilogue, no atomics.
//  B fragments (192 b32/thread) hoisted to registers once.
//  A=[x|h] fp16, 128-wide K chunks (6/step), 3-slot cp.async ring, depth-2.
//  Barrier: flag-array release/poll (warp 0), monolithic end-of-step.

#define TB 256
#define ASTR 68                 // b32 per A row (136 halves)
#define ASLOT_B (32 * ASTR * 4) // 8704 B per ring slot
#define SMEM_BYTES (3 * ASLOT_B) // 26112

static __device__ __half g_x16[128 * 2048 * 256];
static __device__ __half g_h16[2][128 * 512];
static __device__ volatile int g_flagA[128];

__device__ __forceinline__ void cp16(unsigned dst, const void* src) {
    asm volatile("cp.async.cg.shared.global [%0], [%1], 16;\n" ::"r"(dst), "l"(src));
}
__device__ __forceinline__ void cp_commit() { asm volatile("cp.async.commit_group;\n"); }
__device__ __forceinline__ void cp_wait1() { asm volatile("cp.async.wait_group 1;\n"); }

__device__ __forceinline__ void mma_f16(float c[4], unsigned a0, unsigned a1, unsigned a2,
                                        unsigned a3, unsigned b0, unsigned b1) {
    asm volatile(
        "mma.sync.aligned.m16n8k16.row.col.f32.f16.f16.f32 "
        "{%0,%1,%2,%3},{%4,%5,%6,%7},{%8,%9},{%0,%1,%2,%3};"
        : "+f"(c[0]), "+f"(c[1]), "+f"(c[2]), "+f"(c[3])
        : "r"(a0), "r"(a1), "r"(a2), "r"(a3), "r"(b0), "r"(b1));
}
__device__ __forceinline__ void sth(__half* p, __half v) {
    unsigned short u = __half_as_ushort(v);
    asm volatile("st.global.cg.u16 [%0], %1;" ::"l"(p), "h"(u));
}
__device__ __forceinline__ float fsig(float x) { return 1.f / (1.f + __expf(-x)); }
__device__ __forceinline__ float ftanh(float x) {
    float a = fabsf(x);
    float e = __expf(2.f * a);
    float r = 1.f - 2.f / (1.f + e);
    return copysignf(r, x);
}

__global__ void __launch_bounds__(TB, 1)
lstm_persist(const float* __restrict__ W_ix, const float* __restrict__ W_fx,
             const float* __restrict__ W_ox, const float* __restrict__ W_gx,
             const float* __restrict__ W_ih, const float* __restrict__ b_ih,
             const float* __restrict__ W_fh, const float* __restrict__ b_fh,
             const float* __restrict__ W_oh, const float* __restrict__ b_oh,
             const float* __restrict__ W_gh, const float* __restrict__ b_gh) {
    extern __shared__ __align__(16) char smem[];
    const unsigned sb = (unsigned)__cvta_generic_to_shared(smem);

    const int tid = threadIdx.x;
    const int cta = blockIdx.x;
    const int band = cta >> 5;
    const int col = cta & 31;
    const int hc0 = col * 16;
    const int brow0 = band * 32;

    const int lane = tid & 31;
    const int w = tid >> 5;
    const int g = lane >> 2;
    const int tq = lane & 3;
    const int wr0 = (w & 1) * 16;  // warp row base (0/16)
    const int wc0 = (w >> 1) * 16; // warp col base (0/16/32/48)
    const bool odd = tq & 1;

    const float* Whp[4] = {W_ih, W_fh, W_oh, W_gh};
    const float* Wxp[4] = {W_ix, W_fx, W_ox, W_gx};
    const float* bbp[4] = {b_ih, b_fh, b_oh, b_gh};

    // ---- Bias into registers: my acc cols are wc0+nt*8+2tq+{0,1}.
    // n ordering: n = hcl*4 + gate  (hcl = n>>2, gate = n&3)
    float bb[2][2];
#pragma unroll
    for (int nt = 0; nt < 2; ++nt)
#pragma unroll
        for (int j = 0; j < 2; ++j) {
            int c = wc0 + nt * 8 + 2 * tq + j;
            bb[nt][j] = bbp[c & 3][hc0 + (c >> 2)];
        }

    // ---- Hoist B fragments to registers, one 128-K chunk at a time, staged
    // through the A-ring smem (17408 B <= 26112 B).
    unsigned Breg[6][8][2][2];
    {
        __half* Wt = (__half*)smem;
        const unsigned* Wu = (const unsigned*)smem;
#pragma unroll
        for (int kc = 0; kc < 6; ++kc) {
            __syncthreads();
            for (int idx = tid; idx < 64 * 128; idx += TB) {
                int n = idx >> 7;
                int kl = idx & 127;
                int k = kc * 128 + kl;
                int gate = n & 3;
                int hc = hc0 + (n >> 2);
                float v = (k < 256) ? Wxp[gate][hc * 256 + k]
                                    : Whp[gate][hc * 512 + (k - 256)];
                Wt[n * 136 + kl] = __float2half_rn(v);
            }
            __syncthreads();
#pragma unroll
            for (int kk = 0; kk < 8; ++kk)
#pragma unroll
                for (int nt = 0; nt < 2; ++nt) {
                    int wn = (wc0 + nt * 8 + g) * ASTR + kk * 8 + tq;
                    Breg[kc][kk][nt][0] = Wu[wn];
                    Breg[kc][kk][nt][1] = Wu[wn + 4];
                }
        }
        __syncthreads();
    }

    // ---- Cell state in registers (mapping fixed across steps):
    // row = wr0 + g + (odd ? 8 : 0); hc(nt) = hc0 + (wc0+nt*8)/4 + (tq>>1)
    float creg[2] = {0.f, 0.f};
    const int myrow = brow0 + wr0 + g + (odd ? 8 : 0);
    const int myhc0 = hc0 + (wc0 >> 2) + (tq >> 1); // nt adds +2

    // ---- A-chunk staging (2 cp16/thread/chunk)
    const int ar = tid >> 3;
    const int aq = tid & 7;
    const unsigned dA0 = (unsigned)ar * 272 + (unsigned)aq * 16;
    const size_t xrow = ((size_t)(brow0 + ar) * 2048) * 256;
    const size_t hrow = (size_t)(brow0 + ar) * 512;

    auto issue_x = [&](int sti, int ci, int slot) {
        if (sti >= 2048) return;
        unsigned d = sb + (unsigned)slot * ASLOT_B + dA0;
        const __half* s = g_x16 + xrow + (size_t)sti * 256 + ci * 128 + aq * 8;
        cp16(d, s);
        cp16(d + 128, s + 64);
    };
    auto issue_h = [&](int sti, int ci, int slot) {
        unsigned d = sb + (unsigned)slot * ASLOT_B + dA0;
        const __half* s = g_h16[sti & 1] + hrow + (ci - 2) * 128 + aq * 8;
        cp16(d, s);
        cp16(d + 128, s + 64);
    };

    issue_x(0, 0, 0); cp_commit();
    issue_x(0, 1, 1); cp_commit();

    for (int ti = 0; ti < 2048; ++ti) {
        float acc[2][4];
#pragma unroll
        for (int n = 0; n < 2; n++)
#pragma unroll
            for (int j = 0; j < 4; j++) acc[n][j] = 0.f;

#pragma unroll
        for (int kc = 0; kc < 6; ++kc) {
            cp_wait1();
            __syncthreads();
            if (kc < 4) issue_h(ti, kc + 2, (kc + 2) % 3);
            else        issue_x(ti + 1, kc - 4, (kc + 2) % 3);
            cp_commit();

            const unsigned* Au = (const unsigned*)(smem + (kc % 3) * ASLOT_B);
#pragma unroll
            for (int kk = 0; kk < 8; ++kk) {
                int kb = kk * 8 + tq;
                unsigned a0 = Au[(wr0 + g) * ASTR + kb];
                unsigned a1 = Au[(wr0 + g + 8) * ASTR + kb];
                unsigned a2 = Au[(wr0 + g) * ASTR + kb + 4];
                unsigned a3 = Au[(wr0 + g + 8) * ASTR + kb + 4];
                mma_f16(acc[0], a0, a1, a2, a3, Breg[kc][kk][0][0], Breg[kc][kk][0][1]);
                mma_f16(acc[1], a0, a1, a2, a3, Breg[kc][kk][1][0], Breg[kc][kk][1][1]);
            }
        }

        // ---- Register epilogue: bias, gate exchange (2 shfl/nt), cell update
        __half* hcur = g_h16[(ti + 1) & 1];
#pragma unroll
        for (int nt = 0; nt < 2; ++nt) {
            float a0 = acc[nt][0] + bb[nt][0];
            float a1 = acc[nt][1] + bb[nt][1];
            float a2 = acc[nt][2] + bb[nt][0];
            float a3 = acc[nt][3] + bb[nt][1];
            // cols: even thread (2tq,2tq+1)=(zi,zf); odd (zo,zg). rows: 0,1->g; 2,3->g+8
            float t0 = __shfl_xor_sync(0xffffffffu, odd ? a0 : a2, 1);
            float t1 = __shfl_xor_sync(0xffffffffu, odd ? a1 : a3, 1);
            float zi = odd ? t0 : a0;
            float zf = odd ? t1 : a1;
            float zo = odd ? a2 : t0;
            float zg = odd ? a3 : t1;
            float c = ftanh(zg) * fsig(zi) + creg[nt] * fsig(zf);
            creg[nt] = c;
            float h = ftanh(c) * fsig(zo);
            sth(&hcur[(size_t)myrow * 512 + myhc0 + nt * 2], __float2half_rn(h));
        }
        __syncthreads(); // all h stores issued before release

        // ---- Flag-array band barrier (release by tid0, poll by warp 0)
        if (tid == 0) {
            asm volatile("fence.acq_rel.gpu;" ::: "memory");
            g_flagA[cta] = ti + 1;
        }
        if (w == 0) {
            int v;
            do { v = g_flagA[band * 32 + lane]; }
            while (!__all_sync(0xffffffffu, v >= ti + 1));
            asm volatile("fence.acq_rel.gpu;" ::: "memory");
        }
        __syncthreads();
    }
}

__global__ void cvt_x(const float* __restrict__ x) {
    size_t n2 = (size_t)128 * 2048 * 256 / 2;
    size_t stride = (size_t)gridDim.x * blockDim.x;
    for (size_t i = (size_t)blockIdx.x * blockDim.x + threadIdx.x; i < n2; i += stride) {
        float2 v = ((const float2*)x)[i];
        ((__half2*)g_x16)[i] = __floats2half2_rn(v.x, v.y);
    }
}

__global__ void init_k() {
    int i = blockIdx.x * blockDim.x + threadIdx.x;
    if (i < 128) g_flagA[i] = 0;
    for (int j = i; j < 128 * 512 / 2; j += gridDim.x * blockDim.x)
        ((__half2*)g_h16[0])[j] = __floats2half2_rn(0.f, 0.f);
}

// out[b][o] = h_final[b] . W_ph[o] + b_ph[o]; h_final = g_h16[0] (2048 even)
__global__ void __launch_bounds__(256) proj_k(const float* __restrict__ W_ph,
                                              const float* __restrict__ b_ph,
                                              float* __restrict__ out) {
    __shared__ float hs[512];
    int b = blockIdx.x;
    const __half* hrow = g_h16[0] + (size_t)b * 512;
    for (int i = threadIdx.x; i < 512; i += 256) hs[i] = __half2float(hrow[i]);
    __syncthreads();
    int o = threadIdx.x;
    const float* wr = W_ph + o * 512;
    float acc = b_ph[o];
#pragma unroll 8
    for (int k = 0; k < 512; ++k) acc += hs[k] * wr[k];
    out[b * 256 + o] = acc;
}

extern "C" void kernel_launch(void* const* d_in, const int* in_sizes, int n_in,
                              void* d_out, int out_size) {
    (void)in_sizes; (void)n_in; (void)out_size;
    const float* x    = (const float*)d_in[0];
    const float* W_ix = (const float*)d_in[1];
    const float* W_fx = (const float*)d_in[2];
    const float* W_ox = (const float*)d_in[3];
    const float* W_gx = (const float*)d_in[4];
    const float* W_ih = (const float*)d_in[5];
    const float* b_ih = (const float*)d_in[6];
    const float* W_fh = (const float*)d_in[7];
    const float* b_fh = (const float*)d_in[8];
    const float* W_oh = (const float*)d_in[9];
    const float* b_oh = (const float*)d_in[10];
    const float* W_gh = (const float*)d_in[11];
    const float* b_gh = (const float*)d_in[12];
    const float* W_ph = (const float*)d_in[13];
    const float* b_ph = (const float*)d_in[14];

    cudaFuncSetAttribute(lstm_persist, cudaFuncAttributeMaxDynamicSharedMemorySize, SMEM_BYTES);

    cvt_x<<<2048, 256>>>(x);
    init_k<<<256, 256>>>();
    lstm_persist<<<128, TB, SMEM_BYTES>>>(W_ix, W_fx, W_ox, W_gx,
                                          W_ih, b_ih, W_fh, b_fh, W_oh, b_oh, W_gh, b_gh);
    proj_k<<<128, 256>>>(W_ph, b_ph, (float*)d_out);
}

// round 10
// speedup vs baseline: 1.0317x; 1.0317x over previous
#include <cuda_runtime.h>
#include <cuda_fp16.h>
#include <cstdint>
#include <cstddef>

// B=128, S=2048, I=256, H=512, O=256
// Persistent fp16 LSTM, weights-in-registers (proven R8 core):
//  128 CTAs = 4 batch-bands(32 rows) x 32 column-CTAs(16 h-cols x 4 gates).
//  B fragments (192 b32/thread, fp16x2) hoisted to registers ONCE; mma.sync
//  m16n8k16 f32.f16.f16.f32 reads B from regs -> zero weight LDS in mainloop.
//  A=[x|h] fp16, 128-wide K chunks (6/step), 3-slot cp.async ring, depth-2
//  prefetch (wait_group 1); slot = kc%3 compile-time.
//  kc 0..3 issue h chunks (this step), kc 4..5 prefetch next step's x chunks.
//  R10 change (single variable): band barrier = monotone flag-array release
//  (tid0) + warp-0 parallel poll. No atomics, no nanosleep.

#define TB 256
#define ASTR 68                   // b32 per A row (136 halves)
#define ASLOT_B (32 * ASTR * 4)   // 8704 B per ring slot
#define OFF_BS 0                  // 64 floats bias
#define OFF_CST 256               // 512 floats cell state
#define OFF_CS 2304               // 32*68 floats gate preacts (8704 B)
#define OFF_A 11008               // ring: 3 slots (staging aliases this at init)
#define SMEM_BYTES (OFF_A + 3 * ASLOT_B) // 37120

static __device__ __half g_x16[128 * 2048 * 256];
static __device__ __half g_h16[2][128 * 512];
static __device__ volatile int g_flag[128];

__device__ __forceinline__ void cp16(unsigned dst, const void* src) {
    asm volatile("cp.async.cg.shared.global [%0], [%1], 16;\n" ::"r"(dst), "l"(src));
}
__device__ __forceinline__ void cp_commit() { asm volatile("cp.async.commit_group;\n"); }
__device__ __forceinline__ void cp_wait1() { asm volatile("cp.async.wait_group 1;\n"); }

__device__ __forceinline__ void mma_f16(float c[4], unsigned a0, unsigned a1, unsigned a2,
                                        unsigned a3, unsigned b0, unsigned b1) {
    asm volatile(
        "mma.sync.aligned.m16n8k16.row.col.f32.f16.f16.f32 "
        "{%0,%1,%2,%3},{%4,%5,%6,%7},{%8,%9},{%0,%1,%2,%3};"
        : "+f"(c[0]), "+f"(c[1]), "+f"(c[2]), "+f"(c[3])
        : "r"(a0), "r"(a1), "r"(a2), "r"(a3), "r"(b0), "r"(b1));
}
__device__ __forceinline__ void sth(__half* p, __half v) {
    unsigned short u = __half_as_ushort(v);
    asm volatile("st.global.cg.u16 [%0], %1;" ::"l"(p), "h"(u));
}
__device__ __forceinline__ float fsig(float x) { return 1.f / (1.f + __expf(-x)); }
__device__ __forceinline__ float ftanh(float x) {
    float a = fabsf(x);
    float e = __expf(2.f * a);
    float r = 1.f - 2.f / (1.f + e);
    return copysignf(r, x);
}

__global__ void __launch_bounds__(TB, 1)
lstm_persist(const float* __restrict__ W_ix, const float* __restrict__ W_fx,
             const float* __restrict__ W_ox, const float* __restrict__ W_gx,
             const float* __restrict__ W_ih, const float* __restrict__ b_ih,
             const float* __restrict__ W_fh, const float* __restrict__ b_fh,
             const float* __restrict__ W_oh, const float* __restrict__ b_oh,
             const float* __restrict__ W_gh, const float* __restrict__ b_gh) {
    extern __shared__ __align__(16) char smem[];
    float* bs = (float*)(smem + OFF_BS);
    float* cst = (float*)(smem + OFF_CST);
    float* Cs = (float*)(smem + OFF_CS);
    const unsigned sb = (unsigned)__cvta_generic_to_shared(smem);

    const int tid = threadIdx.x;
    const int cta = blockIdx.x;
    const int band = cta >> 5;
    const int col = cta & 31;
    const int hc0 = col * 16;
    const int brow0 = band * 32;

    const int lane = tid & 31;
    const int w = tid >> 5;
    const int g = lane >> 2;
    const int tq = lane & 3;
    const int wr0 = (w & 1) * 16;  // warp row base (0/16)
    const int wc0 = (w >> 1) * 16; // warp col base (0/16/32/48)

    const float* Whp[4] = {W_ih, W_fh, W_oh, W_gh};
    const float* Wxp[4] = {W_ix, W_fx, W_ox, W_gx};
    const float* bbp[4] = {b_ih, b_fh, b_oh, b_gh};

    for (int i = tid; i < 64; i += TB) bs[i] = bbp[i >> 4][hc0 + (i & 15)];
    for (int i = tid; i < 512; i += TB) cst[i] = 0.f;

    // ---- Hoist B fragments into registers, one 128-K chunk at a time,
    // staging through the A-ring smem area (17408 B <= 26112 B).
    unsigned Breg[6][8][2][2];
    {
        __half* Wt = (__half*)(smem + OFF_A);
        const unsigned* Wu = (const unsigned*)(smem + OFF_A);
#pragma unroll
        for (int kc = 0; kc < 6; ++kc) {
            __syncthreads();
            for (int idx = tid; idx < 64 * 128; idx += TB) {
                int n = idx >> 7;
                int kl = idx & 127;
                int k = kc * 128 + kl;
                int gate = n >> 4;
                int hc = hc0 + (n & 15);
                float v = (k < 256) ? Wxp[gate][hc * 256 + k]
                                    : Whp[gate][hc * 512 + (k - 256)];
                Wt[n * 136 + kl] = __float2half_rn(v);
            }
            __syncthreads();
#pragma unroll
            for (int kk = 0; kk < 8; ++kk)
#pragma unroll
                for (int nt = 0; nt < 2; ++nt) {
                    int wn = (wc0 + nt * 8 + g) * ASTR + kk * 8 + tq;
                    Breg[kc][kk][nt][0] = Wu[wn];
                    Breg[kc][kk][nt][1] = Wu[wn + 4];
                }
        }
        __syncthreads();
    }

    // ---- Per-thread A-chunk staging addresses (2 x cp16 per thread per chunk)
    const int ar = tid >> 3;      // 0..31 row
    const int aq = tid & 7;       // 0..7
    const unsigned dA0 = (unsigned)ar * 272 + (unsigned)aq * 16;
    const size_t xrow = ((size_t)(brow0 + ar) * 2048) * 256;
    const size_t hrow = (size_t)(brow0 + ar) * 512;

    auto issue_x = [&](int sti, int ci, int slot) {
        if (sti >= 2048) return;
        unsigned d = sb + OFF_A + (unsigned)slot * ASLOT_B + dA0;
        const __half* s = g_x16 + xrow + (size_t)sti * 256 + ci * 128 + aq * 8;
        cp16(d, s);
        cp16(d + 128, s + 64);
    };
    auto issue_h = [&](int sti, int ci, int slot) {
        unsigned d = sb + OFF_A + (unsigned)slot * ASLOT_B + dA0;
        const __half* s = g_h16[sti & 1] + hrow + (ci - 2) * 128 + aq * 8;
        cp16(d, s);
        cp16(d + 128, s + 64);
    };

    // Prime ring: chunks 0,1 of step 0 (both x).
    issue_x(0, 0, 0); cp_commit();
    issue_x(0, 1, 1); cp_commit();

    for (int ti = 0; ti < 2048; ++ti) {
        float acc[2][4];
#pragma unroll
        for (int n = 0; n < 2; n++)
#pragma unroll
            for (int j = 0; j < 4; j++) acc[n][j] = 0.f;

#pragma unroll
        for (int kc = 0; kc < 6; ++kc) {
            cp_wait1();      // chunk kc resident (pending: kc+1)
            __syncthreads(); // all warps done with mma of kc-1 -> slot free
            if (kc < 4) issue_h(ti, kc + 2, (kc + 2) % 3);
            else        issue_x(ti + 1, kc - 4, (kc + 2) % 3);
            cp_commit();

            const unsigned* Au = (const unsigned*)(smem + OFF_A + (kc % 3) * ASLOT_B);
#pragma unroll
            for (int kk = 0; kk < 8; ++kk) {
                int kb = kk * 8 + tq;
                unsigned a0 = Au[(wr0 + g) * ASTR + kb];
                unsigned a1 = Au[(wr0 + g + 8) * ASTR + kb];
                unsigned a2 = Au[(wr0 + g) * ASTR + kb + 4];
                unsigned a3 = Au[(wr0 + g + 8) * ASTR + kb + 4];
                mma_f16(acc[0], a0, a1, a2, a3, Breg[kc][kk][0][0], Breg[kc][kk][0][1]);
                mma_f16(acc[1], a0, a1, a2, a3, Breg[kc][kk][1][0], Breg[kc][kk][1][1]);
            }
        }

        // ---- Gate preactivations to Cs
        __syncthreads();
#pragma unroll
        for (int nt = 0; nt < 2; ++nt) {
            int c0 = wc0 + nt * 8 + 2 * tq;
            Cs[(wr0 + g) * 68 + c0] = acc[nt][0];
            Cs[(wr0 + g) * 68 + c0 + 1] = acc[nt][1];
            Cs[(wr0 + g + 8) * 68 + c0] = acc[nt][2];
            Cs[(wr0 + g + 8) * 68 + c0 + 1] = acc[nt][3];
        }
        __syncthreads();

        // ---- Cell update (fp32), h store (fp16, st.cg -> L2)
        __half* hcur = g_h16[(ti + 1) & 1];
        for (int it = tid; it < 512; it += TB) {
            int r = it >> 4, hc = it & 15;
            const float* Crow = Cs + r * 68;
            float zi = Crow[hc] + bs[hc];
            float zf = Crow[16 + hc] + bs[16 + hc];
            float zo = Crow[32 + hc] + bs[32 + hc];
            float zg = Crow[48 + hc] + bs[48 + hc];
            float gi_ = fsig(zi);
            float gf = fsig(zf);
            float go = fsig(zo);
            float gg = ftanh(zg);
            float c = gg * gi_ + cst[it] * gf;
            cst[it] = c;
            float h = ftanh(c) * go;
            sth(&hcur[(size_t)(brow0 + r) * 512 + hc0 + hc], __float2half_rn(h));
        }
        __syncthreads(); // all h stores issued (program order) before release

        // ---- R10: flag-array band barrier. Release: tid0 fence + monotone
        // flag store. Poll: warp 0, one flag per lane, __all_sync reduce.
        if (tid == 0) {
            asm volatile("fence.acq_rel.gpu;" ::: "memory");
            g_flag[cta] = ti + 1;
        }
        if (w == 0) {
            int v;
            do { v = g_flag[band * 32 + lane]; }
            while (!__all_sync(0xffffffffu, v >= ti + 1));
            asm volatile("fence.acq_rel.gpu;" ::: "memory");
        }
        __syncthreads();
    }
}

__global__ void cvt_x(const float* __restrict__ x) {
    size_t n2 = (size_t)128 * 2048 * 256 / 2;
    size_t stride = (size_t)gridDim.x * blockDim.x;
    for (size_t i = (size_t)blockIdx.x * blockDim.x + threadIdx.x; i < n2; i += stride) {
        float2 v = ((const float2*)x)[i];
        ((__half2*)g_x16)[i] = __floats2half2_rn(v.x, v.y);
    }
}

__global__ void init_k() {
    int i = blockIdx.x * blockDim.x + threadIdx.x;
    if (i < 128) g_flag[i] = 0;
    for (int j = i; j < 128 * 512 / 2; j += gridDim.x * blockDim.x)
        ((__half2*)g_h16[0])[j] = __floats2half2_rn(0.f, 0.f);
}

// out[b][o] = h_final[b] . W_ph[o] + b_ph[o]; h_final = g_h16[0] (2048 even)
__global__ void __launch_bounds__(256) proj_k(const float* __restrict__ W_ph,
                                              const float* __restrict__ b_ph,
                                              float* __restrict__ out) {
    __shared__ float hs[512];
    int b = blockIdx.x;
    const __half* hrow = g_h16[0] + (size_t)b * 512;
    for (int i = threadIdx.x; i < 512; i += 256) hs[i] = __half2float(hrow[i]);
    __syncthreads();
    int o = threadIdx.x;
    const float* wr = W_ph + o * 512;
    float acc = b_ph[o];
#pragma unroll 8
    for (int k = 0; k < 512; ++k) acc += hs[k] * wr[k];
    out[b * 256 + o] = acc;
}

extern "C" void kernel_launch(void* const* d_in, const int* in_sizes, int n_in,
                              void* d_out, int out_size) {
    (void)in_sizes; (void)n_in; (void)out_size;
    const float* x    = (const float*)d_in[0];
    const float* W_ix = (const float*)d_in[1];
    const float* W_fx = (const float*)d_in[2];
    const float* W_ox = (const float*)d_in[3];
    const float* W_gx = (const float*)d_in[4];
    const float* W_ih = (const float*)d_in[5];
    const float* b_ih = (const float*)d_in[6];
    const float* W_fh = (const float*)d_in[7];
    const float* b_fh = (const float*)d_in[8];
    const float* W_oh = (const float*)d_in[9];
    const float* b_oh = (const float*)d_in[10];
    const float* W_gh = (const float*)d_in[11];
    const float* b_gh = (const float*)d_in[12];
    const float* W_ph = (const float*)d_in[13];
    const float* b_ph = (const float*)d_in[14];

    cudaFuncSetAttribute(lstm_persist, cudaFuncAttributeMaxDynamicSharedMemorySize, SMEM_BYTES);

    cvt_x<<<2048, 256>>>(x);
    init_k<<<256, 256>>>();
    lstm_persist<<<128, TB, SMEM_BYTES>>>(W_ix, W_fx, W_ox, W_gx,
                                          W_ih, b_ih, W_fh, b_fh, W_oh, b_oh, W_gh, b_gh);
    proj_k<<<128, 256>>>(W_ph, b_ph, (float*)d_out);
}

// round 11
// speedup vs baseline: 1.3870x; 1.3444x over previous
#include <cuda_runtime.h>
#include <cuda_fp16.h>
#include <cstdint>
#include <cstddef>

// B=128, S=2048, I=256, H=512, O=256
// Persistent fp16 LSTM, weights-in-registers (proven R8 core).
//  128 CTAs = 4 batch-bands(32 rows) x 32 column-CTAs(16 h-cols x 4 gates).
//  B fragments (192 b32/thread) in registers; mma.sync m16n8k16 f32.f16.f16.f32.
//  R11 change (single variable vs R8): K chunks widened 128 -> 256.
//  3 chunks/step: c0=x(ti) [slot0], c1=h[0:256] [slot1], c2=h[256:512] [slot2].
//  Issue schedule: kc0 -> c2(ti); kc1 -> c0(ti+1); post-barrier -> c1(ti+1).
//  wait_group 1 at each consume; 3 commits/step (balanced).
//  Barrier: R8's atomic-chain + nanosleep (proven; do not touch).

#define TB 256
#define ASTR 132                  // b32 per A row (264 halves: 256 + pad)
#define ASLOT_B (32 * ASTR * 4)   // 16896 B per ring slot
#define OFF_BS 0                  // 64 floats bias
#define OFF_CST 256               // 512 floats cell state
#define OFF_CS 2304               // 32*68 floats gate preacts (8704 B)
#define OFF_A 11008               // 3 slots
#define SMEM_BYTES (OFF_A + 3 * ASLOT_B) // 61696

static __device__ __half g_x16[128 * 2048 * 256];
static __device__ __half g_h16[2][128 * 512];
static __device__ int g_cnt[128];
static __device__ volatile int g_flag[128];

__device__ __forceinline__ void cp16(unsigned dst, const void* src) {
    asm volatile("cp.async.cg.shared.global [%0], [%1], 16;\n" ::"r"(dst), "l"(src));
}
__device__ __forceinline__ void cp_commit() { asm volatile("cp.async.commit_group;\n"); }
__device__ __forceinline__ void cp_wait1() { asm volatile("cp.async.wait_group 1;\n"); }

__device__ __forceinline__ void mma_f16(float c[4], unsigned a0, unsigned a1, unsigned a2,
                                        unsigned a3, unsigned b0, unsigned b1) {
    asm volatile(
        "mma.sync.aligned.m16n8k16.row.col.f32.f16.f16.f32 "
        "{%0,%1,%2,%3},{%4,%5,%6,%7},{%8,%9},{%0,%1,%2,%3};"
        : "+f"(c[0]), "+f"(c[1]), "+f"(c[2]), "+f"(c[3])
        : "r"(a0), "r"(a1), "r"(a2), "r"(a3), "r"(b0), "r"(b1));
}
__device__ __forceinline__ void sth(__half* p, __half v) {
    unsigned short u = __half_as_ushort(v);
    asm volatile("st.global.cg.u16 [%0], %1;" ::"l"(p), "h"(u));
}
__device__ __forceinline__ float fsig(float x) { return 1.f / (1.f + __expf(-x)); }
__device__ __forceinline__ float ftanh(float x) {
    float a = fabsf(x);
    float e = __expf(2.f * a);
    float r = 1.f - 2.f / (1.f + e);
    return copysignf(r, x);
}

__global__ void __launch_bounds__(TB, 1)
lstm_persist(const float* __restrict__ W_ix, const float* __restrict__ W_fx,
             const float* __restrict__ W_ox, const float* __restrict__ W_gx,
             const float* __restrict__ W_ih, const float* __restrict__ b_ih,
             const float* __restrict__ W_fh, const float* __restrict__ b_fh,
             const float* __restrict__ W_oh, const float* __restrict__ b_oh,
             const float* __restrict__ W_gh, const float* __restrict__ b_gh) {
    extern __shared__ __align__(16) char smem[];
    float* bs = (float*)(smem + OFF_BS);
    float* cst = (float*)(smem + OFF_CST);
    float* Cs = (float*)(smem + OFF_CS);
    const unsigned sb = (unsigned)__cvta_generic_to_shared(smem);

    const int tid = threadIdx.x;
    const int cta = blockIdx.x;
    const int band = cta >> 5;
    const int col = cta & 31;
    const int hc0 = col * 16;
    const int brow0 = band * 32;

    const int lane = tid & 31;
    const int w = tid >> 5;
    const int g = lane >> 2;
    const int tq = lane & 3;
    const int wr0 = (w & 1) * 16;  // warp row base (0/16)
    const int wc0 = (w >> 1) * 16; // warp col base (0/16/32/48)

    const float* Whp[4] = {W_ih, W_fh, W_oh, W_gh};
    const float* Wxp[4] = {W_ix, W_fx, W_ox, W_gx};
    const float* bbp[4] = {b_ih, b_fh, b_oh, b_gh};

    for (int i = tid; i < 64; i += TB) bs[i] = bbp[i >> 4][hc0 + (i & 15)];
    for (int i = tid; i < 512; i += TB) cst[i] = 0.f;

    // ---- Hoist B fragments to registers, one 256-K chunk at a time, staged
    // through the A-ring smem (64*264 halves = 33792 B <= 3 slots).
    unsigned Breg[3][16][2][2];
    {
        __half* Wt = (__half*)(smem + OFF_A);
        const unsigned* Wu = (const unsigned*)(smem + OFF_A);
#pragma unroll
        for (int kc = 0; kc < 3; ++kc) {
            __syncthreads();
            for (int idx = tid; idx < 64 * 256; idx += TB) {
                int n = idx >> 8;
                int kl = idx & 255;
                int k = kc * 256 + kl;
                int gate = n >> 4;
                int hc = hc0 + (n & 15);
                float v = (k < 256) ? Wxp[gate][hc * 256 + k]
                                    : Whp[gate][hc * 512 + (k - 256)];
                Wt[n * 264 + kl] = __float2half_rn(v);
            }
            __syncthreads();
#pragma unroll
            for (int kk = 0; kk < 16; ++kk)
#pragma unroll
                for (int nt = 0; nt < 2; ++nt) {
                    int wn = (wc0 + nt * 8 + g) * ASTR + kk * 8 + tq;
                    Breg[kc][kk][nt][0] = Wu[wn];
                    Breg[kc][kk][nt][1] = Wu[wn + 4];
                }
        }
        __syncthreads();
    }

    // ---- A-chunk staging: 4 cp16/thread/chunk (32 rows x 512 B)
    const int ar = tid >> 3; // 0..31 row
    const int aq = tid & 7;  // 0..7
    const unsigned dA0 = (unsigned)ar * (ASTR * 4) + (unsigned)aq * 16;
    const size_t xrow = ((size_t)(brow0 + ar) * 2048) * 256;
    const size_t hrow = (size_t)(brow0 + ar) * 512;

    auto issue_x = [&](int sti) { // c0 -> slot0
        if (sti >= 2048) return;
        unsigned d = sb + OFF_A + dA0;
        const __half* s = g_x16 + xrow + (size_t)sti * 256 + aq * 8;
#pragma unroll
        for (int u = 0; u < 4; ++u) cp16(d + u * 128, s + u * 64);
    };
    auto issue_h = [&](int sti, int ci) { // ci in {1,2} -> slot ci
        unsigned d = sb + OFF_A + (unsigned)ci * ASLOT_B + dA0;
        const __half* s = g_h16[sti & 1] + hrow + (ci - 1) * 256 + aq * 8;
#pragma unroll
        for (int u = 0; u < 4; ++u) cp16(d + u * 128, s + u * 64);
    };

    // Prime: c0(0) and c1(0) in flight (h(0) zeroed by init_k).
    issue_x(0); cp_commit();
    issue_h(0, 1); cp_commit();

    for (int ti = 0; ti < 2048; ++ti) {
        float acc[2][4];
#pragma unroll
        for (int n = 0; n < 2; n++)
#pragma unroll
            for (int j = 0; j < 4; j++) acc[n][j] = 0.f;

#pragma unroll
        for (int kc = 0; kc < 3; ++kc) {
            cp_wait1();      // chunk kc resident (1 group may stay pending)
            __syncthreads(); // all warps done reading the slot being refilled
            if (kc == 0) { issue_h(ti, 2); cp_commit(); }
            else if (kc == 1) { issue_x(ti + 1); cp_commit(); }
            // kc == 2: no issue (c1(ti+1) must wait for the barrier)

            const unsigned* Au = (const unsigned*)(smem + OFF_A + kc * ASLOT_B);
#pragma unroll
            for (int kk = 0; kk < 16; ++kk) {
                int kb = kk * 8 + tq;
                unsigned a0 = Au[(wr0 + g) * ASTR + kb];
                unsigned a1 = Au[(wr0 + g + 8) * ASTR + kb];
                unsigned a2 = Au[(wr0 + g) * ASTR + kb + 4];
                unsigned a3 = Au[(wr0 + g + 8) * ASTR + kb + 4];
                mma_f16(acc[0], a0, a1, a2, a3, Breg[kc][kk][0][0], Breg[kc][kk][0][1]);
                mma_f16(acc[1], a0, a1, a2, a3, Breg[kc][kk][1][0], Breg[kc][kk][1][1]);
            }
        }

        // ---- Gate preactivations to Cs
        __syncthreads();
#pragma unroll
        for (int nt = 0; nt < 2; ++nt) {
            int c0 = wc0 + nt * 8 + 2 * tq;
            Cs[(wr0 + g) * 68 + c0] = acc[nt][0];
            Cs[(wr0 + g) * 68 + c0 + 1] = acc[nt][1];
            Cs[(wr0 + g + 8) * 68 + c0] = acc[nt][2];
            Cs[(wr0 + g + 8) * 68 + c0 + 1] = acc[nt][3];
        }
        __syncthreads();

        // ---- Cell update (fp32), h store (fp16, st.cg -> L2)
        __half* hcur = g_h16[(ti + 1) & 1];
        for (int it = tid; it < 512; it += TB) {
            int r = it >> 4, hc = it & 15;
            const float* Crow = Cs + r * 68;
            float zi = Crow[hc] + bs[hc];
            float zf = Crow[16 + hc] + bs[16 + hc];
            float zo = Crow[32 + hc] + bs[32 + hc];
            float zg = Crow[48 + hc] + bs[48 + hc];
            float gi_ = fsig(zi);
            float gf = fsig(zf);
            float go = fsig(zo);
            float gg = ftanh(zg);
            float c = gg * gi_ + cst[it] * gf;
            cst[it] = c;
            float h = ftanh(c) * go;
            sth(&hcur[(size_t)(brow0 + r) * 512 + hc0 + hc], __float2half_rn(h));
        }
        __syncthreads(); // all h stores issued before release

        // ---- Band barrier: R8's proven atomic chain + nanosleep
        if (tid == 0) {
            asm volatile("fence.acq_rel.gpu;" ::: "memory");
            int prev = atomicAdd(&g_cnt[band * 32], 1);
            if (prev == 31) {
                atomicExch(&g_cnt[band * 32], 0);
                g_flag[band * 32] = ti + 1;
            } else {
                while (g_flag[band * 32] < ti + 1) { __nanosleep(64); }
                asm volatile("fence.acq_rel.gpu;" ::: "memory");
            }
        }
        __syncthreads();

        // ---- Post-barrier: first h chunk of next step
        if (ti + 1 < 2048) issue_h(ti + 1, 1);
        cp_commit();
    }
}

__global__ void cvt_x(const float* __restrict__ x) {
    size_t n2 = (size_t)128 * 2048 * 256 / 2;
    size_t stride = (size_t)gridDim.x * blockDim.x;
    for (size_t i = (size_t)blockIdx.x * blockDim.x + threadIdx.x; i < n2; i += stride) {
        float2 v = ((const float2*)x)[i];
        ((__half2*)g_x16)[i] = __floats2half2_rn(v.x, v.y);
    }
}

__global__ void init_k() {
    int i = blockIdx.x * blockDim.x + threadIdx.x;
    if (i < 128) {
        g_cnt[i] = 0;
        g_flag[i] = 0;
    }
    for (int j = i; j < 128 * 512 / 2; j += gridDim.x * blockDim.x)
        ((__half2*)g_h16[0])[j] = __floats2half2_rn(0.f, 0.f);
}

// out[b][o] = h_final[b] . W_ph[o] + b_ph[o]; h_final = g_h16[0] (2048 even)
__global__ void __launch_bounds__(256) proj_k(const float* __restrict__ W_ph,
                                              const float* __restrict__ b_ph,
                                              float* __restrict__ out) {
    __shared__ float hs[512];
    int b = blockIdx.x;
    const __half* hrow = g_h16[0] + (size_t)b * 512;
    for (int i = threadIdx.x; i < 512; i += 256) hs[i] = __half2float(hrow[i]);
    __syncthreads();
    int o = threadIdx.x;
    const float* wr = W_ph + o * 512;
    float acc = b_ph[o];
#pragma unroll 8
    for (int k = 0; k < 512; ++k) acc += hs[k] * wr[k];
    out[b * 256 + o] = acc;
}

extern "C" void kernel_launch(void* const* d_in, const int* in_sizes, int n_in,
                              void* d_out, int out_size) {
    (void)in_sizes; (void)n_in; (void)out_size;
    const float* x    = (const float*)d_in[0];
    const float* W_ix = (const float*)d_in[1];
    const float* W_fx = (const float*)d_in[2];
    const float* W_ox = (const float*)d_in[3];
    const float* W_gx = (const float*)d_in[4];
    const float* W_ih = (const float*)d_in[5];
    const float* b_ih = (const float*)d_in[6];
    const float* W_fh = (const float*)d_in[7];
    const float* b_fh = (const float*)d_in[8];
    const float* W_oh = (const float*)d_in[9];
    const float* b_oh = (const float*)d_in[10];
    const float* W_gh = (const float*)d_in[11];
    const float* b_gh = (const float*)d_in[12];
    const float* W_ph = (const float*)d_in[13];
    const float* b_ph = (const float*)d_in[14];

    cudaFuncSetAttribute(lstm_persist, cudaFuncAttributeMaxDynamicSharedMemorySize, SMEM_BYTES);

    cvt_x<<<2048, 256>>>(x);
    init_k<<<256, 256>>>();
    lstm_persist<<<128, TB, SMEM_BYTES>>>(W_ix, W_fx, W_ox, W_gx,
                                          W_ih, b_ih, W_fh, b_fh, W_oh, b_oh, W_gh, b_gh);
    proj_k<<<128, 256>>>(W_ph, b_ph, (float*)d_out);
}